// round 1
// baseline (speedup 1.0000x reference)
#include <cuda_runtime.h>
#include <math.h>

// ---------------- problem constants ----------------
#define TS   63        // scan length (T-1)
#define BB   256       // batch
#define OBSD 512
#define ACTD 32
#define EMBD 1024
#define DETD 1024
#define STOD 256
#define RR   (TS*BB)   // 16128 rows when batched over time

// ---------------- device scratch (static, no allocs) ----------------
__device__ float g_embh[RR*EMBD];          // enc hidden
__device__ float g_emb [RR*EMBD];          // emb for all t
__device__ float g_post_emb[RR*2*STOD];    // emb @ post_w[1024:] + post_b
__device__ float g_gia [RR*3*DETD];        // a_t @ wih_a^T + gru_bih
__device__ float g_h_all[RR*DETD];         // unmasked h_next per t
__device__ float g_z_all[RR*STOD];         // z_post per t
__device__ float g_feat[RR*(DETD+STOD)];   // [h_next | z]
__device__ float g_H1  [RR*2048];          // relu(feat @ [dec_w1|rew_w1])
__device__ float g_pred[RR*OBSD];          // pred_obs
__device__ float g_S[BB*4096];             // per-step h @ Wh  (prior|post_h|gh)
__device__ float g_G[BB*3*DETD];           // per-step gi
__device__ float g_h[BB*DETD];             // recurrent state
__device__ float g_kl[RR];
__device__ float g_recon[RR];
__device__ float g_rewl[RR];
// transformed weights
__device__ float g_Wh[DETD*4096];          // [prior_w | post_w_h | whh^T]
__device__ float g_bh[4096];               // [prior_b | 0 | gru_bhh]
__device__ float g_wihzT[STOD*3*DETD];
__device__ float g_wihaT[ACTD*3*DETD];
__device__ float g_W1f[(DETD+STOD)*2048];  // [dec_w1 | rew_w1]
__device__ float g_b1f[2048];

// ---------------- generic fp32 GEMM: C = act(A@B + bias + addend) ----------------
// A: [M,K] row-major (lda), B: [K,N] row-major (ldb), C: [M,N] (ldc)
// Requires M%64==0, N%64==0, K%16==0 (all shapes here satisfy this).
__global__ void gemm_k(const float* __restrict__ A, int lda,
                       const float* __restrict__ Bm, int ldb,
                       float* __restrict__ C, int ldc,
                       const float* __restrict__ bias,
                       const float* __restrict__ addend, int ldadd,
                       int K, int relu)
{
    __shared__ float As[16][64];
    __shared__ float Bs[16][64];
    int tid = threadIdx.x;
    int tx = tid & 15, ty = tid >> 4;
    long brow = (long)blockIdx.y * 64, bcol = (long)blockIdx.x * 64;

    float acc[4][4] = {};

    const int am = tid >> 2, ak = (tid & 3) * 4;
    const float* Ag = A + (brow + am) * (long)lda + ak;
    const int bk = tid >> 4, bc = (tid & 15) * 4;
    const float* Bg = Bm + (long)bk * ldb + bcol + bc;

    for (int k0 = 0; k0 < K; k0 += 16) {
        float4 av = *(const float4*)(Ag + k0);
        As[ak+0][am] = av.x; As[ak+1][am] = av.y;
        As[ak+2][am] = av.z; As[ak+3][am] = av.w;
        float4 bv = *(const float4*)(Bg + (long)k0 * ldb);
        *(float4*)&Bs[bk][bc] = bv;
        __syncthreads();
        #pragma unroll
        for (int k = 0; k < 16; k++) {
            float4 a4 = *(const float4*)&As[k][ty*4];
            float4 b4 = *(const float4*)&Bs[k][tx*4];
            float ar[4] = {a4.x, a4.y, a4.z, a4.w};
            float br[4] = {b4.x, b4.y, b4.z, b4.w};
            #pragma unroll
            for (int i = 0; i < 4; i++)
                #pragma unroll
                for (int j = 0; j < 4; j++)
                    acc[i][j] += ar[i] * br[j];
        }
        __syncthreads();
    }

    #pragma unroll
    for (int i = 0; i < 4; i++) {
        long row = brow + ty*4 + i;
        long col = bcol + tx*4;
        float ov[4];
        #pragma unroll
        for (int j = 0; j < 4; j++) {
            float v = acc[i][j];
            if (bias)   v += bias[col + j];
            if (addend) v += addend[row * (long)ldadd + col + j];
            if (relu)   v = fmaxf(v, 0.0f);
            ov[j] = v;
        }
        float4 o4 = make_float4(ov[0], ov[1], ov[2], ov[3]);
        *(float4*)&C[row * (long)ldc + col] = o4;
    }
}

// ---------------- weight prep ----------------
__global__ void prep_wh_k(const float* __restrict__ prior_w, const float* __restrict__ prior_b,
                          const float* __restrict__ post_w,
                          const float* __restrict__ gru_whh, const float* __restrict__ gru_bhh)
{
    long idx = (long)blockIdx.x * blockDim.x + threadIdx.x;
    if (idx < (long)DETD*4096) {
        int k = (int)(idx >> 12), n = (int)(idx & 4095);
        float v;
        if (n < 512)       v = prior_w[k*512 + n];
        else if (n < 1024) v = post_w[k*512 + (n - 512)];
        else               v = gru_whh[(long)(n-1024)*DETD + k];
        g_Wh[idx] = v;
    }
    if (idx < 4096) {
        int n = (int)idx;
        g_bh[n] = (n < 512) ? prior_b[n] : (n < 1024 ? 0.0f : gru_bhh[n-1024]);
    }
}

__global__ void prep_wih_k(const float* __restrict__ gru_wih)
{
    long idx = (long)blockIdx.x * blockDim.x + threadIdx.x;
    if (idx >= (long)(STOD+ACTD)*3*DETD) return;
    int k = (int)(idx / (3*DETD)), n = (int)(idx % (3*DETD));
    float v = gru_wih[(long)n*(STOD+ACTD) + k];
    if (k < STOD) g_wihzT[(long)k*3*DETD + n] = v;
    else          g_wihaT[(long)(k-STOD)*3*DETD + n] = v;
}

__global__ void prep_w1f_k(const float* __restrict__ dec_w1, const float* __restrict__ dec_b1,
                           const float* __restrict__ rew_w1, const float* __restrict__ rew_b1)
{
    long idx = (long)blockIdx.x * blockDim.x + threadIdx.x;
    if (idx < (long)(DETD+STOD)*2048) {
        int k = (int)(idx >> 11), n = (int)(idx & 2047);
        g_W1f[idx] = (n < 1024) ? dec_w1[(long)k*1024 + n] : rew_w1[(long)k*1024 + (n-1024)];
    }
    if (idx < 2048) {
        int n = (int)idx;
        g_b1f[n] = (n < 1024) ? dec_b1[n] : rew_b1[n-1024];
    }
}

// ---------------- per-step elementwise ----------------
// posterior + z + kl. grid=(BB), block=(STOD)
__global__ void post_z_k(const float* __restrict__ eps, int t)
{
    int b = blockIdx.x, j = threadIdx.x;
    const float* Sr = g_S + (long)b*4096;
    const float* pe = g_post_emb + ((long)t*BB + b)*2*STOD;
    float pm = Sr[j], pl = Sr[STOD + j];
    float qm = Sr[512 + j]        + pe[j];
    float ql = Sr[512 + STOD + j] + pe[STOD + j];
    float e  = eps[((long)t*BB + b)*STOD + j];
    float z  = qm + e * expf(ql);
    g_z_all[((long)t*BB + b)*STOD + j] = z;

    float vq = expf(2.0f*ql), vp = expf(2.0f*pl);
    float d  = qm - pm;
    float kl = pl - ql + (vq + d*d) / (vp + 1e-8f) - 1.0f;

    __shared__ float red[STOD];
    red[j] = kl; __syncthreads();
    for (int s = STOD/2; s > 0; s >>= 1) {
        if (j < s) red[j] += red[j + s];
        __syncthreads();
    }
    if (j == 0) g_kl[t*BB + b] = 0.5f * red[0];
}

// GRU update. grid*block = BB*DETD
__global__ void gru_k(const unsigned char* __restrict__ dones, int t)
{
    int idx = blockIdx.x * blockDim.x + threadIdx.x;
    int b = idx >> 10, n = idx & 1023;
    const float* Gr = g_G + (long)b*3*DETD;
    const float* Sr = g_S + (long)b*4096;
    float ir = Gr[n], iz = Gr[1024 + n], inn = Gr[2048 + n];
    float hr = Sr[1024 + n], hz = Sr[2048 + n], hn = Sr[3072 + n];
    float r  = 1.0f / (1.0f + expf(-(ir + hr)));
    float u  = 1.0f / (1.0f + expf(-(iz + hz)));
    float nn = tanhf(inn + r * hn);
    float hp = g_h[idx];
    float hnew = (1.0f - u) * nn + u * hp;
    g_h_all[(long)t*BB*DETD + idx] = hnew;                 // unmasked, used by decoder
    float mask = dones[t*BB + b] ? 0.0f : 1.0f;
    g_h[idx] = hnew * mask;                                // carried
}

// ---------------- batched epilogue ----------------
__global__ void feat_k()
{
    long idx = (long)blockIdx.x * blockDim.x + threadIdx.x;
    if (idx >= (long)RR*(DETD+STOD)) return;
    long r = idx / (DETD+STOD);
    int  c = (int)(idx % (DETD+STOD));
    g_feat[idx] = (c < DETD) ? g_h_all[r*DETD + c] : g_z_all[r*STOD + (c - DETD)];
}

// per-row recon loss. grid=RR, block=128
__global__ void recon_k(const float* __restrict__ obs)
{
    int r = blockIdx.x, t = threadIdx.x;
    const float* p = g_pred + (long)r*OBSD;
    const float* o = obs + ((long)r + BB)*OBSD;   // obs[1:] aligned: row r -> obs row r+B
    float s = 0.0f;
    for (int i = t; i < OBSD; i += 128) { float d = p[i] - o[i]; s += d*d; }
    __shared__ float red[128];
    red[t] = s; __syncthreads();
    for (int st = 64; st > 0; st >>= 1) {
        if (t < st) red[t] += red[t + st];
        __syncthreads();
    }
    if (t == 0) g_recon[r] = red[0] / (float)OBSD;
}

// per-row reward head + loss. grid=RR, block=256
__global__ void rew_k(const float* __restrict__ rewards,
                      const float* __restrict__ rew_w2, const float* __restrict__ rew_b2)
{
    int r = blockIdx.x, t = threadIdx.x;
    const float* hrow = g_H1 + (long)r*2048 + 1024;
    float s = 0.0f;
    for (int i = t; i < 1024; i += 256) s += hrow[i] * rew_w2[i];
    __shared__ float red[256];
    red[t] = s; __syncthreads();
    for (int st = 128; st > 0; st >>= 1) {
        if (t < st) red[t] += red[t + st];
        __syncthreads();
    }
    if (t == 0) {
        float pred = red[0] + rew_b2[0];
        float d = pred - rewards[r];
        g_rewl[r] = d*d;
    }
}

__global__ void final_k(float* __restrict__ out)
{
    int t = threadIdx.x;
    float a = 0, b = 0, c = 0;
    for (int i = t; i < RR; i += 256) { a += g_recon[i]; b += g_rewl[i]; c += g_kl[i]; }
    __shared__ float sa[256], sb[256], sc[256];
    sa[t] = a; sb[t] = b; sc[t] = c; __syncthreads();
    for (int s = 128; s > 0; s >>= 1) {
        if (t < s) { sa[t] += sa[t+s]; sb[t] += sb[t+s]; sc[t] += sc[t+s]; }
        __syncthreads();
    }
    if (t == 0) {
        float recon = sa[0] / (float)RR;
        float rew   = sb[0] / (float)RR;
        float kl    = sc[0] / (float)RR;
        out[0] = recon + rew + kl;  // KL_SCALE = 1
        out[1] = recon;
        out[2] = rew;
        out[3] = kl;
    }
}

// ---------------- host ----------------
static inline void run_gemm(const float* A, int lda, const float* B, int ldb,
                            float* C, int ldc, const float* bias,
                            const float* addend, int ldadd,
                            int M, int N, int K, int relu)
{
    dim3 grid(N/64, M/64);
    gemm_k<<<grid, 256>>>(A, lda, B, ldb, C, ldc, bias, addend, ldadd, K, relu);
}

extern "C" void kernel_launch(void* const* d_in, const int* in_sizes, int n_in,
                              void* d_out, int out_size)
{
    const float* obs     = (const float*)d_in[0];
    const float* actions = (const float*)d_in[1];
    const float* rewards = (const float*)d_in[2];
    const unsigned char* dones = (const unsigned char*)d_in[3];
    const float* eps     = (const float*)d_in[4];
    const float* enc_w1  = (const float*)d_in[5];
    const float* enc_b1  = (const float*)d_in[6];
    const float* enc_w2  = (const float*)d_in[7];
    const float* enc_b2  = (const float*)d_in[8];
    const float* gru_wih = (const float*)d_in[9];
    const float* gru_whh = (const float*)d_in[10];
    const float* gru_bih = (const float*)d_in[11];
    const float* gru_bhh = (const float*)d_in[12];
    const float* prior_w = (const float*)d_in[13];
    const float* prior_b = (const float*)d_in[14];
    const float* post_w  = (const float*)d_in[15];
    const float* post_b  = (const float*)d_in[16];
    const float* dec_w1  = (const float*)d_in[17];
    const float* dec_b1  = (const float*)d_in[18];
    const float* dec_w2  = (const float*)d_in[19];
    const float* dec_b2  = (const float*)d_in[20];
    const float* rew_w1  = (const float*)d_in[21];
    const float* rew_b1  = (const float*)d_in[22];
    const float* rew_w2  = (const float*)d_in[23];
    const float* rew_b2  = (const float*)d_in[24];
    float* out = (float*)d_out;

    // device addresses of scratch symbols (query only, no allocation)
    #define SYM(p, s) float* p; cudaGetSymbolAddress((void**)&p, s)
    SYM(p_embh, g_embh);   SYM(p_emb, g_emb);     SYM(p_post_emb, g_post_emb);
    SYM(p_gia, g_gia);     SYM(p_z_all, g_z_all); SYM(p_S, g_S);
    SYM(p_G, g_G);         SYM(p_h, g_h);         SYM(p_feat, g_feat);
    SYM(p_H1, g_H1);       SYM(p_pred, g_pred);
    SYM(p_Wh, g_Wh);       SYM(p_bh, g_bh);
    SYM(p_wihzT, g_wihzT); SYM(p_wihaT, g_wihaT);
    SYM(p_W1f, g_W1f);     SYM(p_b1f, g_b1f);
    #undef SYM

    // init recurrent state
    cudaMemsetAsync(p_h, 0, (size_t)BB*DETD*sizeof(float));

    // weight prep
    {
        long n = (long)DETD*4096;
        prep_wh_k<<<(unsigned)((n + 255)/256), 256>>>(prior_w, prior_b, post_w, gru_whh, gru_bhh);
        long n2 = (long)(STOD+ACTD)*3*DETD;
        prep_wih_k<<<(unsigned)((n2 + 255)/256), 256>>>(gru_wih);
        long n3 = (long)(DETD+STOD)*2048;
        prep_w1f_k<<<(unsigned)((n3 + 255)/256), 256>>>(dec_w1, dec_b1, rew_w1, rew_b1);
    }

    // ---- Phase A: time-batched precompute ----
    // embh = relu(obs[:-1] @ enc_w1 + enc_b1)
    run_gemm(obs, OBSD, enc_w1, EMBD, p_embh, EMBD, enc_b1, nullptr, 0, RR, EMBD, OBSD, 1);
    // emb = relu(embh @ enc_w2 + enc_b2)
    run_gemm(p_embh, EMBD, enc_w2, EMBD, p_emb, EMBD, enc_b2, nullptr, 0, RR, EMBD, EMBD, 1);
    // post_emb = emb @ post_w[1024:,:] + post_b
    run_gemm(p_emb, EMBD, post_w + (size_t)DETD*2*STOD, 2*STOD, p_post_emb, 2*STOD,
             post_b, nullptr, 0, RR, 2*STOD, EMBD, 0);
    // gia = actions[:-1] @ wih_a^T + gru_bih
    run_gemm(actions, ACTD, p_wihaT, 3*DETD, p_gia, 3*DETD, gru_bih, nullptr, 0,
             RR, 3*DETD, ACTD, 0);

    // ---- Phase B: sequential recurrence ----
    for (int t = 0; t < TS; t++) {
        // S = h @ [prior_w | post_w_h | whh^T] + [prior_b | 0 | gru_bhh]
        run_gemm(p_h, DETD, p_Wh, 4096, p_S, 4096, p_bh, nullptr, 0, BB, 4096, DETD, 0);
        post_z_k<<<BB, STOD>>>(eps, t);
        // G = z @ wih_z^T + gia[t]
        run_gemm(p_z_all + (size_t)t*BB*STOD, STOD, p_wihzT, 3*DETD, p_G, 3*DETD,
                 nullptr, p_gia + (size_t)t*BB*3*DETD, 3*DETD, BB, 3*DETD, STOD, 0);
        gru_k<<<(BB*DETD)/256, 256>>>(dones, t);
    }

    // ---- Phase C: time-batched decoder / reward / losses ----
    {
        long n = (long)RR*(DETD+STOD);
        feat_k<<<(unsigned)((n + 255)/256), 256>>>();
    }
    // H1 = relu(feat @ [dec_w1 | rew_w1] + [dec_b1 | rew_b1])
    run_gemm(p_feat, DETD+STOD, p_W1f, 2048, p_H1, 2048, p_b1f, nullptr, 0,
             RR, 2048, DETD+STOD, 1);
    // pred_obs = H1[:, :1024] @ dec_w2 + dec_b2
    run_gemm(p_H1, 2048, dec_w2, OBSD, p_pred, OBSD, dec_b2, nullptr, 0,
             RR, OBSD, EMBD, 0);
    recon_k<<<RR, 128>>>(obs);
    rew_k<<<RR, 256>>>(rewards, rew_w2, rew_b2);
    final_k<<<1, 256>>>(out);

    (void)in_sizes; (void)n_in; (void)out_size;
}

// round 6
// speedup vs baseline: 1.6386x; 1.6386x over previous
#include <cuda_runtime.h>
#include <math.h>
#include <stdint.h>

// ---------------- problem constants ----------------
#define TS   63
#define BB   256
#define OBSD 512
#define ACTD 32
#define EMBD 1024
#define DETD 1024
#define STOD 256
#define RR   (TS*BB)
#define FEATD (DETD+STOD)   // 1280

// ---------------- device scratch ----------------
__device__ float g_embh[RR*EMBD];
__device__ float g_emb [RR*EMBD];
__device__ float g_post_emb[RR*2*STOD];
__device__ float g_gia [RR*3*DETD];
__device__ float g_feat[RR*FEATD];          // [h | z] per (t,b) row
__device__ float g_H1  [RR*2048];
__device__ float g_pred[RR*OBSD];
__device__ float g_S[BB*4096];
__device__ float g_G[BB*3*DETD];
__device__ float g_h[BB*DETD];
__device__ float g_kl[RR];
__device__ float g_recon[RR];
__device__ float g_rewl[RR];
// weights, pre-transposed to [N,K] (K-major)
__device__ float g_WhT[4096*DETD];
__device__ float g_bh[4096];
__device__ float g_encw1T[EMBD*OBSD];
__device__ float g_encw2T[EMBD*EMBD];
__device__ float g_postEmbT[2*STOD*EMBD];
__device__ float g_decw2T[OBSD*EMBD];
__device__ float g_W1fT[2048*FEATD];
__device__ float g_b1f[2048];

__device__ __forceinline__ uint32_t f2tf(float f) {
    uint32_t r;
    asm("cvt.rna.tf32.f32 %0, %1;" : "=r"(r) : "f"(f));
    return r;
}

// ---------------- tf32 mma.sync GEMM ----------------
// C[M,N] = act(A[M,K] @ B[N,K]^T + bias [+ addend])
// Block tile 128x128, 8 warps (warp tile 32x64), K-chunk 32.
// SMEM stored in fragment order:
//   A: idx = ((kb*8 + mb)*32 + lane)*4 + j   (uint4 per lane per (kb,mb))
//      lane = (m%8)*4 + (k8%4), j = ((m%16)>=8) + 2*(k8>=4)
//   B: idx = ((kb*16 + nb)*32 + lane)*2 + j  (uint2 per lane per (kb,nb))
//      lane = (n%8)*4 + (k8%4), j = (k8>=4)
__global__ void __launch_bounds__(256, 1) mma_gemm(
    const float* __restrict__ A, int lda,
    const float* __restrict__ B, int ldb,
    float* __restrict__ C, int ldc,
    const float* __restrict__ bias,
    const float* __restrict__ addend, int ldadd,
    int K, int relu)
{
    __shared__ __align__(16) uint32_t As[4096];
    __shared__ __align__(16) uint32_t Bs[4096];

    const int tid  = threadIdx.x;
    const int wid  = tid >> 5;
    const int lane = tid & 31;
    const int warp_m = wid & 3;       // 4 warps along M: 32 rows each
    const int warp_n = wid >> 2;      // 2 warps along N: 64 cols each
    const long brow = (long)blockIdx.y * 128;
    const long bcol = (long)blockIdx.x * 128;

    const int nch = K >> 5;

    float c[2][8][4];
    #pragma unroll
    for (int im = 0; im < 2; im++)
        #pragma unroll
        for (int in_ = 0; in_ < 8; in_++)
            #pragma unroll
            for (int j = 0; j < 4; j++) c[im][in_][j] = 0.0f;

    // per-thread fill coordinates (4 float4 each for A and B)
    int fr[4], fkc[4];
    #pragma unroll
    for (int i = 0; i < 4; i++) {
        int lin = i*256 + tid;
        fr[i]  = lin >> 3;        // 0..127
        fkc[i] = (lin & 7) << 2;  // 0,4,..,28
    }

    float4 sA[4], sB[4];
    // prologue: load chunk 0
    #pragma unroll
    for (int i = 0; i < 4; i++) {
        sA[i] = *(const float4*)(A + (brow + fr[i])*(long)lda + fkc[i]);
        sB[i] = *(const float4*)(B + (bcol + fr[i])*(long)ldb + fkc[i]);
    }

    for (int cch = 0; cch < nch; cch++) {
        // ---- store staged chunk into SMEM in fragment order ----
        #pragma unroll
        for (int i = 0; i < 4; i++) {
            int r = fr[i], kc = fkc[i];
            int kb = kc >> 3;
            int jhalf = (kc >> 2) & 1;     // k8 >= 4 ?
            // A
            {
                int mb = r >> 4;
                int lb = (r & 7) << 2;
                int ja = ((r >> 3) & 1) + (jhalf << 1);
                uint32_t* base = &As[(((kb << 3) + mb) << 5) << 2];  // ((kb*8+mb)*32)*4
                base[((lb + 0) << 2) + ja] = f2tf(sA[i].x);
                base[((lb + 1) << 2) + ja] = f2tf(sA[i].y);
                base[((lb + 2) << 2) + ja] = f2tf(sA[i].z);
                base[((lb + 3) << 2) + ja] = f2tf(sA[i].w);
            }
            // B
            {
                int nb = r >> 3;
                int lb = (r & 7) << 2;
                uint32_t* base = &Bs[(((kb << 4) + nb) << 5) << 1];  // ((kb*16+nb)*32)*2
                base[((lb + 0) << 1) + jhalf] = f2tf(sB[i].x);
                base[((lb + 1) << 1) + jhalf] = f2tf(sB[i].y);
                base[((lb + 2) << 1) + jhalf] = f2tf(sB[i].z);
                base[((lb + 3) << 1) + jhalf] = f2tf(sB[i].w);
            }
        }
        __syncthreads();

        // ---- prefetch next chunk ----
        if (cch + 1 < nch) {
            int k0 = (cch + 1) << 5;
            #pragma unroll
            for (int i = 0; i < 4; i++) {
                sA[i] = *(const float4*)(A + (brow + fr[i])*(long)lda + k0 + fkc[i]);
                sB[i] = *(const float4*)(B + (bcol + fr[i])*(long)ldb + k0 + fkc[i]);
            }
        }

        // ---- compute ----
        #pragma unroll
        for (int kb = 0; kb < 4; kb++) {
            uint4 af[2];
            #pragma unroll
            for (int im = 0; im < 2; im++)
                af[im] = ((const uint4*)As)[(kb*8 + warp_m*2 + im)*32 + lane];
            uint2 bf[8];
            #pragma unroll
            for (int in_ = 0; in_ < 8; in_++)
                bf[in_] = ((const uint2*)Bs)[(kb*16 + warp_n*8 + in_)*32 + lane];
            #pragma unroll
            for (int im = 0; im < 2; im++)
                #pragma unroll
                for (int in_ = 0; in_ < 8; in_++) {
                    asm volatile(
                        "mma.sync.aligned.m16n8k8.row.col.f32.tf32.tf32.f32 "
                        "{%0,%1,%2,%3}, {%4,%5,%6,%7}, {%8,%9}, {%0,%1,%2,%3};"
                        : "+f"(c[im][in_][0]), "+f"(c[im][in_][1]),
                          "+f"(c[im][in_][2]), "+f"(c[im][in_][3])
                        : "r"(af[im].x), "r"(af[im].y), "r"(af[im].z), "r"(af[im].w),
                          "r"(bf[in_].x), "r"(bf[in_].y));
                }
        }
        __syncthreads();
    }

    // ---- epilogue ----
    const int gid = lane >> 2;   // groupID
    const int tig = lane & 3;
    #pragma unroll
    for (int im = 0; im < 2; im++) {
        long r0 = brow + warp_m*32 + im*16 + gid;
        #pragma unroll
        for (int in_ = 0; in_ < 8; in_++) {
            long cb = bcol + warp_n*64 + in_*8 + tig*2;
            #pragma unroll
            for (int half = 0; half < 2; half++) {
                long row = r0 + half*8;
                float v0 = c[im][in_][half*2 + 0];
                float v1 = c[im][in_][half*2 + 1];
                if (bias) { v0 += bias[cb]; v1 += bias[cb + 1]; }
                if (addend) {
                    float2 ad = *(const float2*)(addend + row*(long)ldadd + cb);
                    v0 += ad.x; v1 += ad.y;
                }
                if (relu) { v0 = fmaxf(v0, 0.f); v1 = fmaxf(v1, 0.f); }
                *(float2*)(C + row*(long)ldc + cb) = make_float2(v0, v1);
            }
        }
    }
}

// ---------------- weight prep (transposes into [N,K]) ----------------
__global__ void transpose_k(float* __restrict__ dst, const float* __restrict__ src, int K, int N)
{
    long idx = (long)blockIdx.x * blockDim.x + threadIdx.x;
    if (idx >= (long)K * N) return;
    int n = (int)(idx / K), k = (int)(idx % K);
    dst[idx] = src[(long)k * N + n];
}

__global__ void prep_whT_k(const float* __restrict__ prior_w, const float* __restrict__ prior_b,
                           const float* __restrict__ post_w,
                           const float* __restrict__ gru_whh, const float* __restrict__ gru_bhh)
{
    long idx = (long)blockIdx.x * blockDim.x + threadIdx.x;
    if (idx < (long)4096 * DETD) {
        int n = (int)(idx >> 10), k = (int)(idx & 1023);
        float v;
        if (n < 512)       v = prior_w[k*512 + n];
        else if (n < 1024) v = post_w[k*512 + (n - 512)];
        else               v = gru_whh[(long)(n - 1024)*DETD + k];
        g_WhT[idx] = v;
    }
    if (idx < 4096) {
        int n = (int)idx;
        g_bh[n] = (n < 512) ? prior_b[n] : (n < 1024 ? 0.0f : gru_bhh[n - 1024]);
    }
}

__global__ void prep_w1fT_k(const float* __restrict__ dec_w1, const float* __restrict__ dec_b1,
                            const float* __restrict__ rew_w1, const float* __restrict__ rew_b1)
{
    long idx = (long)blockIdx.x * blockDim.x + threadIdx.x;
    if (idx < (long)2048 * FEATD) {
        int n = (int)(idx / FEATD), k = (int)(idx % FEATD);
        g_W1fT[idx] = (n < 1024) ? dec_w1[(long)k*1024 + n] : rew_w1[(long)k*1024 + (n - 1024)];
    }
    if (idx < 2048) {
        int n = (int)idx;
        g_b1f[n] = (n < 1024) ? dec_b1[n] : rew_b1[n - 1024];
    }
}

__global__ void prep_postEmbT_k(const float* __restrict__ post_w)
{
    long idx = (long)blockIdx.x * blockDim.x + threadIdx.x;
    if (idx >= (long)2*STOD*EMBD) return;
    int n = (int)(idx >> 10), k = (int)(idx & 1023);
    g_postEmbT[idx] = post_w[(long)(1024 + k)*512 + n];
}

// ---------------- per-step elementwise ----------------
__global__ void post_z_k(const float* __restrict__ eps, int t)
{
    int b = blockIdx.x, j = threadIdx.x;
    const float* Sr = g_S + (long)b*4096;
    const float* pe = g_post_emb + ((long)t*BB + b)*2*STOD;
    float pm = Sr[j], pl = Sr[STOD + j];
    float qm = Sr[512 + j]        + pe[j];
    float ql = Sr[512 + STOD + j] + pe[STOD + j];
    float e  = eps[((long)t*BB + b)*STOD + j];
    float z  = qm + e * expf(ql);
    g_feat[((long)t*BB + b)*FEATD + DETD + j] = z;

    float vq = expf(2.0f*ql), vp = expf(2.0f*pl);
    float d  = qm - pm;
    float kl = pl - ql + (vq + d*d) / (vp + 1e-8f) - 1.0f;

    __shared__ float red[STOD];
    red[j] = kl; __syncthreads();
    for (int s = STOD/2; s > 0; s >>= 1) {
        if (j < s) red[j] += red[j + s];
        __syncthreads();
    }
    if (j == 0) g_kl[t*BB + b] = 0.5f * red[0];
}

__global__ void gru_k(const unsigned char* __restrict__ dones, int t)
{
    int idx = blockIdx.x * blockDim.x + threadIdx.x;
    int b = idx >> 10, n = idx & 1023;
    const float* Gr = g_G + (long)b*3*DETD;
    const float* Sr = g_S + (long)b*4096;
    float ir = Gr[n], iz = Gr[1024 + n], inn = Gr[2048 + n];
    float hr = Sr[1024 + n], hz = Sr[2048 + n], hn = Sr[3072 + n];
    float r  = 1.0f / (1.0f + expf(-(ir + hr)));
    float u  = 1.0f / (1.0f + expf(-(iz + hz)));
    float nn = tanhf(inn + r * hn);
    float hp = g_h[idx];
    float hnew = (1.0f - u) * nn + u * hp;
    g_feat[((long)t*BB + b)*FEATD + n] = hnew;
    float mask = dones[t*BB + b] ? 0.0f : 1.0f;
    g_h[idx] = hnew * mask;
}

// ---------------- batched loss kernels ----------------
__global__ void recon_k(const float* __restrict__ obs)
{
    int r = blockIdx.x, t = threadIdx.x;
    const float* p = g_pred + (long)r*OBSD;
    const float* o = obs + ((long)r + BB)*OBSD;
    float s = 0.0f;
    for (int i = t; i < OBSD; i += 128) { float d = p[i] - o[i]; s += d*d; }
    __shared__ float red[128];
    red[t] = s; __syncthreads();
    for (int st = 64; st > 0; st >>= 1) {
        if (t < st) red[t] += red[t + st];
        __syncthreads();
    }
    if (t == 0) g_recon[r] = red[0] / (float)OBSD;
}

__global__ void rew_k(const float* __restrict__ rewards,
                      const float* __restrict__ rew_w2, const float* __restrict__ rew_b2)
{
    int r = blockIdx.x, t = threadIdx.x;
    const float* hrow = g_H1 + (long)r*2048 + 1024;
    float s = 0.0f;
    for (int i = t; i < 1024; i += 256) s += hrow[i] * rew_w2[i];
    __shared__ float red[256];
    red[t] = s; __syncthreads();
    for (int st = 128; st > 0; st >>= 1) {
        if (t < st) red[t] += red[t + st];
        __syncthreads();
    }
    if (t == 0) {
        float pred = red[0] + rew_b2[0];
        float d = pred - rewards[r];
        g_rewl[r] = d*d;
    }
}

__global__ void final_k(float* __restrict__ out)
{
    int t = threadIdx.x;
    float a = 0, b = 0, c = 0;
    for (int i = t; i < RR; i += 256) { a += g_recon[i]; b += g_rewl[i]; c += g_kl[i]; }
    __shared__ float sa[256], sb[256], sc[256];
    sa[t] = a; sb[t] = b; sc[t] = c; __syncthreads();
    for (int s = 128; s > 0; s >>= 1) {
        if (t < s) { sa[t] += sa[t+s]; sb[t] += sb[t+s]; sc[t] += sc[t+s]; }
        __syncthreads();
    }
    if (t == 0) {
        float recon = sa[0] / (float)RR;
        float rew   = sb[0] / (float)RR;
        float kl    = sc[0] / (float)RR;
        out[0] = recon + rew + kl;
        out[1] = recon;
        out[2] = rew;
        out[3] = kl;
    }
}

// ---------------- host ----------------
static inline void run_mm(const float* A, int lda, const float* B, int ldb,
                          float* C, int ldc, const float* bias,
                          const float* addend, int ldadd, int M, int N, int K, int relu)
{
    dim3 grid(N/128, M/128);
    mma_gemm<<<grid, 256>>>(A, lda, B, ldb, C, ldc, bias, addend, ldadd, K, relu);
}

extern "C" void kernel_launch(void* const* d_in, const int* in_sizes, int n_in,
                              void* d_out, int out_size)
{
    const float* obs     = (const float*)d_in[0];
    const float* actions = (const float*)d_in[1];
    const float* rewards = (const float*)d_in[2];
    const unsigned char* dones = (const unsigned char*)d_in[3];
    const float* eps     = (const float*)d_in[4];
    const float* enc_w1  = (const float*)d_in[5];
    const float* enc_b1  = (const float*)d_in[6];
    const float* enc_w2  = (const float*)d_in[7];
    const float* enc_b2  = (const float*)d_in[8];
    const float* gru_wih = (const float*)d_in[9];
    const float* gru_whh = (const float*)d_in[10];
    const float* gru_bih = (const float*)d_in[11];
    const float* gru_bhh = (const float*)d_in[12];
    const float* prior_w = (const float*)d_in[13];
    const float* prior_b = (const float*)d_in[14];
    const float* post_w  = (const float*)d_in[15];
    const float* post_b  = (const float*)d_in[16];
    const float* dec_w1  = (const float*)d_in[17];
    const float* dec_b1  = (const float*)d_in[18];
    const float* dec_w2  = (const float*)d_in[19];
    const float* dec_b2  = (const float*)d_in[20];
    const float* rew_w1  = (const float*)d_in[21];
    const float* rew_b1  = (const float*)d_in[22];
    const float* rew_w2  = (const float*)d_in[23];
    const float* rew_b2  = (const float*)d_in[24];
    float* out = (float*)d_out;

    #define SYM(p, s) float* p; cudaGetSymbolAddress((void**)&p, s)
    SYM(p_embh, g_embh);     SYM(p_emb, g_emb);       SYM(p_post_emb, g_post_emb);
    SYM(p_gia, g_gia);       SYM(p_S, g_S);           SYM(p_G, g_G);
    SYM(p_h, g_h);           SYM(p_feat, g_feat);
    SYM(p_H1, g_H1);         SYM(p_pred, g_pred);
    SYM(p_WhT, g_WhT);       SYM(p_bh, g_bh);
    SYM(p_encw1T, g_encw1T); SYM(p_encw2T, g_encw2T);
    SYM(p_postEmbT, g_postEmbT); SYM(p_decw2T, g_decw2T);
    SYM(p_W1fT, g_W1fT);     SYM(p_b1f, g_b1f);
    #undef SYM

    cudaMemsetAsync(p_h, 0, (size_t)BB*DETD*sizeof(float));

    // ---- weight prep (transpose to [N,K]) ----
    {
        long n;
        n = (long)EMBD*OBSD;
        transpose_k<<<(unsigned)((n+255)/256), 256>>>(p_encw1T, enc_w1, OBSD, EMBD);
        n = (long)EMBD*EMBD;
        transpose_k<<<(unsigned)((n+255)/256), 256>>>(p_encw2T, enc_w2, EMBD, EMBD);
        n = (long)OBSD*EMBD;
        transpose_k<<<(unsigned)((n+255)/256), 256>>>(p_decw2T, dec_w2, EMBD, OBSD);
        n = (long)2*STOD*EMBD;
        prep_postEmbT_k<<<(unsigned)((n+255)/256), 256>>>(post_w);
        n = (long)4096*DETD;
        prep_whT_k<<<(unsigned)((n+255)/256), 256>>>(prior_w, prior_b, post_w, gru_whh, gru_bhh);
        n = (long)2048*FEATD;
        prep_w1fT_k<<<(unsigned)((n+255)/256), 256>>>(dec_w1, dec_b1, rew_w1, rew_b1);
    }

    // ---- Phase A: time-batched precompute ----
    run_mm(obs, OBSD, p_encw1T, OBSD, p_embh, EMBD, enc_b1, nullptr, 0,
           RR, EMBD, OBSD, 1);
    run_mm(p_embh, EMBD, p_encw2T, EMBD, p_emb, EMBD, enc_b2, nullptr, 0,
           RR, EMBD, EMBD, 1);
    run_mm(p_emb, EMBD, p_postEmbT, EMBD, p_post_emb, 2*STOD, post_b, nullptr, 0,
           RR, 2*STOD, EMBD, 0);
    run_mm(actions, ACTD, gru_wih + STOD, STOD+ACTD, p_gia, 3*DETD, gru_bih, nullptr, 0,
           RR, 3*DETD, ACTD, 0);

    // ---- Phase B: sequential recurrence ----
    for (int t = 0; t < TS; t++) {
        run_mm(p_h, DETD, p_WhT, DETD, p_S, 4096, p_bh, nullptr, 0,
               BB, 4096, DETD, 0);
        post_z_k<<<BB, STOD>>>(eps, t);
        run_mm(p_feat + (size_t)t*BB*FEATD + DETD, FEATD, gru_wih, STOD+ACTD,
               p_G, 3*DETD, nullptr, p_gia + (size_t)t*BB*3*DETD, 3*DETD,
               BB, 3*DETD, STOD, 0);
        gru_k<<<(BB*DETD)/256, 256>>>(dones, t);
    }

    // ---- Phase C: time-batched decoder / reward / losses ----
    run_mm(p_feat, FEATD, p_W1fT, FEATD, p_H1, 2048, p_b1f, nullptr, 0,
           RR, 2048, FEATD, 1);
    run_mm(p_H1, 2048, p_decw2T, EMBD, p_pred, OBSD, dec_b2, nullptr, 0,
           RR, OBSD, EMBD, 0);
    recon_k<<<RR, 128>>>(obs);
    rew_k<<<RR, 256>>>(rewards, rew_w2, rew_b2);
    final_k<<<1, 256>>>(out);

    (void)in_sizes; (void)n_in; (void)out_size;
}

// round 7
// speedup vs baseline: 2.4142x; 1.4733x over previous
#include <cuda_runtime.h>
#include <math.h>
#include <stdint.h>

// ---------------- problem constants ----------------
#define TS   63
#define BB   256
#define OBSD 512
#define ACTD 32
#define EMBD 1024
#define DETD 1024
#define STOD 256
#define RR   (TS*BB)
#define FEATD (DETD+STOD)   // 1280

// ---------------- device scratch ----------------
__device__ float g_embh[RR*EMBD];
__device__ float g_emb [RR*EMBD];
__device__ float g_post_emb[RR*2*STOD];     // [RR, 512]
__device__ float g_gia [RR*3*DETD];
__device__ float g_feat[RR*FEATD];          // [h | z] per (t,b) row
__device__ float g_H1  [RR*2048];
__device__ float g_pred[RR*OBSD];
__device__ float g_S_all[(size_t)RR*4096];  // per-step h-projections, kept for batched KL
__device__ float g_G[BB*3*DETD];
__device__ float g_h[BB*DETD];
__device__ float g_kl[RR];
__device__ float g_recon[RR];
__device__ float g_rewl[RR];
// weights, pre-transposed to [N,K] (K-major)
__device__ float g_WhT[4096*DETD];
__device__ float g_bh[4096];
__device__ float g_encw1T[EMBD*OBSD];
__device__ float g_encw2T[EMBD*EMBD];
__device__ float g_postEmbT[2*STOD*EMBD];
__device__ float g_decw2T[OBSD*EMBD];
__device__ float g_W1fT[2048*FEATD];
__device__ float g_b1f[2048];

__device__ __forceinline__ uint32_t f2tf(float f) {
    uint32_t r;
    asm("cvt.rna.tf32.f32 %0, %1;" : "=r"(r) : "f"(f));
    return r;
}
// swizzled word index inside a [rows x 32] float smem tile
__device__ __forceinline__ int swz(int r, int k) {
    return r*32 + (k ^ ((r & 7) << 2));
}

// ---------------- tf32 mma.sync GEMM ----------------
// C[M,N] = act(A[M,K] @ B[N,K]^T + bias [+ addend])
// Block tile BM x 128, 8 warps, K-chunk 32.
// SMEM: natural K-major rows of 32 floats with XOR swizzle (conflict-free STS.128 + LDS.32).
// Optional z-fusion: when zS != nullptr, A rows are the posterior sample
//   z(b,j) = (zS[b][512+j]+zpe[b][j]) + zeps[b][j]*exp(zS[b][768+j]+zpe[b][256+j])
// computed on the fly; CTAs with blockIdx.x==0 also persist z into zfeat.
template<int BM>
__global__ void __launch_bounds__(256) mma_gemm(
    const float* __restrict__ A, int lda,
    const float* __restrict__ B, int ldb,
    float* __restrict__ C, int ldc,
    const float* __restrict__ bias,
    const float* __restrict__ addend, int ldadd,
    int K, int relu,
    const float* __restrict__ zS, const float* __restrict__ zpe,
    const float* __restrict__ zeps, float* __restrict__ zfeat)
{
    __shared__ __align__(16) uint32_t As[BM*32];
    __shared__ __align__(16) uint32_t Bs[128*32];

    const int tid = threadIdx.x;
    const int wid = tid >> 5, lane = tid & 31;
    constexpr int WMN  = BM/32;       // warps along M (rows 32 each)
    constexpr int WNN  = 8/WMN;       // warps along N
    constexpr int NCOL = 128/WNN;     // cols per warp
    constexpr int NAT  = NCOL/8;      // n-atoms per warp
    const int warp_m = wid % WMN;
    const int warp_n = wid / WMN;
    const int gid = lane >> 2, tig = lane & 3;
    const long brow = (long)blockIdx.y * BM;
    const long bcol = (long)blockIdx.x * 128;
    const int nch = K >> 5;
    const bool zf = (zS != nullptr);

    float c[2][NAT][4];
    #pragma unroll
    for (int im = 0; im < 2; im++)
        #pragma unroll
        for (int in_ = 0; in_ < NAT; in_++)
            #pragma unroll
            for (int j = 0; j < 4; j++) c[im][in_][j] = 0.0f;

    constexpr int NA = BM/32;         // float4 per thread for A tile
    int fr[NA], fkc[NA];
    #pragma unroll
    for (int i = 0; i < NA; i++) {
        int lin = i*256 + tid;
        fr[i]  = lin >> 3;
        fkc[i] = (lin & 7) << 2;
    }
    int gr[4], gkc[4];                // B tile: 4 float4 per thread
    #pragma unroll
    for (int i = 0; i < 4; i++) {
        int lin = i*256 + tid;
        gr[i]  = lin >> 3;
        gkc[i] = (lin & 7) << 2;
    }

    float4 sA[NA], sB[4];

    // ---- chunk loader (A: plain or z-fused) ----
    #define LOAD_CHUNK(k0)                                                          \
    do {                                                                            \
        if (!zf) {                                                                  \
            _Pragma("unroll")                                                       \
            for (int i = 0; i < NA; i++)                                            \
                sA[i] = *(const float4*)(A + (brow + fr[i])*(long)lda + (k0) + fkc[i]); \
        } else {                                                                    \
            _Pragma("unroll")                                                       \
            for (int i = 0; i < NA; i++) {                                          \
                long b = brow + fr[i];                                              \
                int  j = (k0) + fkc[i];                                             \
                float4 qm = *(const float4*)(zS + b*4096 + 512 + j);                \
                float4 p1 = *(const float4*)(zpe + b*512 + j);                      \
                float4 ql = *(const float4*)(zS + b*4096 + 768 + j);                \
                float4 p2 = *(const float4*)(zpe + b*512 + 256 + j);                \
                float4 e  = *(const float4*)(zeps + b*256 + j);                     \
                float4 z;                                                           \
                z.x = (qm.x + p1.x) + e.x * expf(ql.x + p2.x);                      \
                z.y = (qm.y + p1.y) + e.y * expf(ql.y + p2.y);                      \
                z.z = (qm.z + p1.z) + e.z * expf(ql.z + p2.z);                      \
                z.w = (qm.w + p1.w) + e.w * expf(ql.w + p2.w);                      \
                if (blockIdx.x == 0)                                                \
                    *(float4*)(zfeat + b*FEATD + DETD + j) = z;                     \
                sA[i] = z;                                                          \
            }                                                                       \
        }                                                                           \
        _Pragma("unroll")                                                           \
        for (int i = 0; i < 4; i++)                                                 \
            sB[i] = *(const float4*)(B + (bcol + gr[i])*(long)ldb + (k0) + gkc[i]); \
    } while (0)

    LOAD_CHUNK(0);

    for (int cch = 0; cch < nch; cch++) {
        // ---- store staged chunk (coalesced STS.128, swizzled) ----
        #pragma unroll
        for (int i = 0; i < NA; i++) {
            uint4 t;
            t.x = f2tf(sA[i].x); t.y = f2tf(sA[i].y);
            t.z = f2tf(sA[i].z); t.w = f2tf(sA[i].w);
            *(uint4*)&As[swz(fr[i], fkc[i])] = t;
        }
        #pragma unroll
        for (int i = 0; i < 4; i++) {
            uint4 t;
            t.x = f2tf(sB[i].x); t.y = f2tf(sB[i].y);
            t.z = f2tf(sB[i].z); t.w = f2tf(sB[i].w);
            *(uint4*)&Bs[swz(gr[i], gkc[i])] = t;
        }
        __syncthreads();

        // ---- prefetch next chunk ----
        if (cch + 1 < nch) {
            int k0 = (cch + 1) << 5;
            LOAD_CHUNK(k0);
        }

        // ---- compute ----
        #pragma unroll
        for (int kb = 0; kb < 4; kb++) {
            const int kk = kb*8 + tig;
            uint32_t af[2][4];
            #pragma unroll
            for (int ia = 0; ia < 2; ia++) {
                int m0 = warp_m*32 + ia*16 + gid;
                int x  = (m0 & 7) << 2;
                af[ia][0] = As[m0*32     + (kk     ^ x)];
                af[ia][1] = As[(m0+8)*32 + (kk     ^ x)];
                af[ia][2] = As[m0*32     + ((kk+4) ^ x)];
                af[ia][3] = As[(m0+8)*32 + ((kk+4) ^ x)];
            }
            uint32_t bf[NAT][2];
            #pragma unroll
            for (int nb = 0; nb < NAT; nb++) {
                int n = warp_n*NCOL + nb*8 + gid;
                int x = (n & 7) << 2;
                bf[nb][0] = Bs[n*32 + (kk     ^ x)];
                bf[nb][1] = Bs[n*32 + ((kk+4) ^ x)];
            }
            #pragma unroll
            for (int im = 0; im < 2; im++)
                #pragma unroll
                for (int in_ = 0; in_ < NAT; in_++) {
                    asm volatile(
                        "mma.sync.aligned.m16n8k8.row.col.f32.tf32.tf32.f32 "
                        "{%0,%1,%2,%3}, {%4,%5,%6,%7}, {%8,%9}, {%0,%1,%2,%3};"
                        : "+f"(c[im][in_][0]), "+f"(c[im][in_][1]),
                          "+f"(c[im][in_][2]), "+f"(c[im][in_][3])
                        : "r"(af[im][0]), "r"(af[im][1]), "r"(af[im][2]), "r"(af[im][3]),
                          "r"(bf[in_][0]), "r"(bf[in_][1]));
                }
        }
        __syncthreads();
    }
    #undef LOAD_CHUNK

    // ---- epilogue ----
    #pragma unroll
    for (int im = 0; im < 2; im++) {
        long r0 = brow + warp_m*32 + im*16 + gid;
        #pragma unroll
        for (int in_ = 0; in_ < NAT; in_++) {
            long cb = bcol + warp_n*NCOL + in_*8 + tig*2;
            #pragma unroll
            for (int half = 0; half < 2; half++) {
                long row = r0 + half*8;
                float v0 = c[im][in_][half*2 + 0];
                float v1 = c[im][in_][half*2 + 1];
                if (bias) { v0 += bias[cb]; v1 += bias[cb + 1]; }
                if (addend) {
                    float2 ad = *(const float2*)(addend + row*(long)ldadd + cb);
                    v0 += ad.x; v1 += ad.y;
                }
                if (relu) { v0 = fmaxf(v0, 0.f); v1 = fmaxf(v1, 0.f); }
                *(float2*)(C + row*(long)ldc + cb) = make_float2(v0, v1);
            }
        }
    }
}

// ---------------- weight prep (transposes into [N,K]) ----------------
__global__ void transpose_k(float* __restrict__ dst, const float* __restrict__ src, int K, int N)
{
    long idx = (long)blockIdx.x * blockDim.x + threadIdx.x;
    if (idx >= (long)K * N) return;
    int n = (int)(idx / K), k = (int)(idx % K);
    dst[idx] = src[(long)k * N + n];
}

__global__ void prep_whT_k(const float* __restrict__ prior_w, const float* __restrict__ prior_b,
                           const float* __restrict__ post_w,
                           const float* __restrict__ gru_whh, const float* __restrict__ gru_bhh)
{
    long idx = (long)blockIdx.x * blockDim.x + threadIdx.x;
    if (idx < (long)4096 * DETD) {
        int n = (int)(idx >> 10), k = (int)(idx & 1023);
        float v;
        if (n < 512)       v = prior_w[k*512 + n];
        else if (n < 1024) v = post_w[k*512 + (n - 512)];
        else               v = gru_whh[(long)(n - 1024)*DETD + k];
        g_WhT[idx] = v;
    }
    if (idx < 4096) {
        int n = (int)idx;
        g_bh[n] = (n < 512) ? prior_b[n] : (n < 1024 ? 0.0f : gru_bhh[n - 1024]);
    }
}

__global__ void prep_w1fT_k(const float* __restrict__ dec_w1, const float* __restrict__ dec_b1,
                            const float* __restrict__ rew_w1, const float* __restrict__ rew_b1)
{
    long idx = (long)blockIdx.x * blockDim.x + threadIdx.x;
    if (idx < (long)2048 * FEATD) {
        int n = (int)(idx / FEATD), k = (int)(idx % FEATD);
        g_W1fT[idx] = (n < 1024) ? dec_w1[(long)k*1024 + n] : rew_w1[(long)k*1024 + (n - 1024)];
    }
    if (idx < 2048) {
        int n = (int)idx;
        g_b1f[n] = (n < 1024) ? dec_b1[n] : rew_b1[n - 1024];
    }
}

__global__ void prep_postEmbT_k(const float* __restrict__ post_w)
{
    long idx = (long)blockIdx.x * blockDim.x + threadIdx.x;
    if (idx >= (long)2*STOD*EMBD) return;
    int n = (int)(idx >> 10), k = (int)(idx & 1023);
    g_postEmbT[idx] = post_w[(long)(1024 + k)*512 + n];
}

// ---------------- per-step elementwise ----------------
// GRU update; h_next written straight into feat layout. grid*block = BB*DETD
__global__ void gru_k(const unsigned char* __restrict__ dones, int t)
{
    int idx = blockIdx.x * blockDim.x + threadIdx.x;
    int b = idx >> 10, n = idx & 1023;
    const float* Gr = g_G + (long)b*3*DETD;
    const float* Sr = g_S_all + ((size_t)t*BB + b)*4096;
    float ir = Gr[n], iz = Gr[1024 + n], inn = Gr[2048 + n];
    float hr = Sr[1024 + n], hz = Sr[2048 + n], hn = Sr[3072 + n];
    float r  = 1.0f / (1.0f + expf(-(ir + hr)));
    float u  = 1.0f / (1.0f + expf(-(iz + hz)));
    float nn = tanhf(inn + r * hn);
    float hp = g_h[idx];
    float hnew = (1.0f - u) * nn + u * hp;
    g_feat[((long)t*BB + b)*FEATD + n] = hnew;
    float mask = dones[t*BB + b] ? 0.0f : 1.0f;
    g_h[idx] = hnew * mask;
}

// batched KL over all rows. grid=RR, block=STOD
__global__ void klbatch_k()
{
    int row = blockIdx.x, j = threadIdx.x;
    const float* Sr = g_S_all + (size_t)row*4096;
    const float* pe = g_post_emb + (long)row*512;
    float pm = Sr[j], pl = Sr[STOD + j];
    float qm = Sr[512 + j] + pe[j];
    float ql = Sr[768 + j] + pe[256 + j];
    float vq = expf(2.0f*ql), vp = expf(2.0f*pl);
    float d  = qm - pm;
    float kl = pl - ql + (vq + d*d) / (vp + 1e-8f) - 1.0f;

    __shared__ float red[STOD];
    red[j] = kl; __syncthreads();
    for (int s = STOD/2; s > 0; s >>= 1) {
        if (j < s) red[j] += red[j + s];
        __syncthreads();
    }
    if (j == 0) g_kl[row] = 0.5f * red[0];
}

// ---------------- batched loss kernels ----------------
__global__ void recon_k(const float* __restrict__ obs)
{
    int r = blockIdx.x, t = threadIdx.x;
    const float* p = g_pred + (long)r*OBSD;
    const float* o = obs + ((long)r + BB)*OBSD;
    float s = 0.0f;
    for (int i = t; i < OBSD; i += 128) { float d = p[i] - o[i]; s += d*d; }
    __shared__ float red[128];
    red[t] = s; __syncthreads();
    for (int st = 64; st > 0; st >>= 1) {
        if (t < st) red[t] += red[t + st];
        __syncthreads();
    }
    if (t == 0) g_recon[r] = red[0] / (float)OBSD;
}

__global__ void rew_k(const float* __restrict__ rewards,
                      const float* __restrict__ rew_w2, const float* __restrict__ rew_b2)
{
    int r = blockIdx.x, t = threadIdx.x;
    const float* hrow = g_H1 + (long)r*2048 + 1024;
    float s = 0.0f;
    for (int i = t; i < 1024; i += 256) s += hrow[i] * rew_w2[i];
    __shared__ float red[256];
    red[t] = s; __syncthreads();
    for (int st = 128; st > 0; st >>= 1) {
        if (t < st) red[t] += red[t + st];
        __syncthreads();
    }
    if (t == 0) {
        float pred = red[0] + rew_b2[0];
        float d = pred - rewards[r];
        g_rewl[r] = d*d;
    }
}

__global__ void final_k(float* __restrict__ out)
{
    int t = threadIdx.x;
    float a = 0, b = 0, c = 0;
    for (int i = t; i < RR; i += 256) { a += g_recon[i]; b += g_rewl[i]; c += g_kl[i]; }
    __shared__ float sa[256], sb[256], sc[256];
    sa[t] = a; sb[t] = b; sc[t] = c; __syncthreads();
    for (int s = 128; s > 0; s >>= 1) {
        if (t < s) { sa[t] += sa[t+s]; sb[t] += sb[t+s]; sc[t] += sc[t+s]; }
        __syncthreads();
    }
    if (t == 0) {
        float recon = sa[0] / (float)RR;
        float rew   = sb[0] / (float)RR;
        float kl    = sc[0] / (float)RR;
        out[0] = recon + rew + kl;
        out[1] = recon;
        out[2] = rew;
        out[3] = kl;
    }
}

// ---------------- host ----------------
static inline void run128(const float* A, int lda, const float* B, int ldb,
                          float* C, int ldc, const float* bias,
                          const float* addend, int ldadd, int M, int N, int K, int relu)
{
    dim3 grid(N/128, M/128);
    mma_gemm<128><<<grid, 256>>>(A, lda, B, ldb, C, ldc, bias, addend, ldadd, K, relu,
                                 nullptr, nullptr, nullptr, nullptr);
}
static inline void run64(const float* A, int lda, const float* B, int ldb,
                         float* C, int ldc, const float* bias,
                         const float* addend, int ldadd, int M, int N, int K, int relu,
                         const float* zS = nullptr, const float* zpe = nullptr,
                         const float* zeps = nullptr, float* zfeat = nullptr)
{
    dim3 grid(N/128, M/64);
    mma_gemm<64><<<grid, 256>>>(A, lda, B, ldb, C, ldc, bias, addend, ldadd, K, relu,
                                zS, zpe, zeps, zfeat);
}

extern "C" void kernel_launch(void* const* d_in, const int* in_sizes, int n_in,
                              void* d_out, int out_size)
{
    const float* obs     = (const float*)d_in[0];
    const float* actions = (const float*)d_in[1];
    const float* rewards = (const float*)d_in[2];
    const unsigned char* dones = (const unsigned char*)d_in[3];
    const float* eps     = (const float*)d_in[4];
    const float* enc_w1  = (const float*)d_in[5];
    const float* enc_b1  = (const float*)d_in[6];
    const float* enc_w2  = (const float*)d_in[7];
    const float* enc_b2  = (const float*)d_in[8];
    const float* gru_wih = (const float*)d_in[9];
    const float* gru_whh = (const float*)d_in[10];
    const float* gru_bih = (const float*)d_in[11];
    const float* gru_bhh = (const float*)d_in[12];
    const float* prior_w = (const float*)d_in[13];
    const float* prior_b = (const float*)d_in[14];
    const float* post_w  = (const float*)d_in[15];
    const float* post_b  = (const float*)d_in[16];
    const float* dec_w1  = (const float*)d_in[17];
    const float* dec_b1  = (const float*)d_in[18];
    const float* dec_w2  = (const float*)d_in[19];
    const float* dec_b2  = (const float*)d_in[20];
    const float* rew_w1  = (const float*)d_in[21];
    const float* rew_b1  = (const float*)d_in[22];
    const float* rew_w2  = (const float*)d_in[23];
    const float* rew_b2  = (const float*)d_in[24];
    float* out = (float*)d_out;

    #define SYM(p, s) float* p; cudaGetSymbolAddress((void**)&p, s)
    SYM(p_embh, g_embh);     SYM(p_emb, g_emb);       SYM(p_post_emb, g_post_emb);
    SYM(p_gia, g_gia);       SYM(p_S_all, g_S_all);   SYM(p_G, g_G);
    SYM(p_h, g_h);           SYM(p_feat, g_feat);
    SYM(p_H1, g_H1);         SYM(p_pred, g_pred);
    SYM(p_WhT, g_WhT);       SYM(p_bh, g_bh);
    SYM(p_encw1T, g_encw1T); SYM(p_encw2T, g_encw2T);
    SYM(p_postEmbT, g_postEmbT); SYM(p_decw2T, g_decw2T);
    SYM(p_W1fT, g_W1fT);     SYM(p_b1f, g_b1f);
    #undef SYM

    cudaMemsetAsync(p_h, 0, (size_t)BB*DETD*sizeof(float));

    // ---- weight prep (transpose to [N,K]) ----
    {
        long n;
        n = (long)EMBD*OBSD;
        transpose_k<<<(unsigned)((n+255)/256), 256>>>(p_encw1T, enc_w1, OBSD, EMBD);
        n = (long)EMBD*EMBD;
        transpose_k<<<(unsigned)((n+255)/256), 256>>>(p_encw2T, enc_w2, EMBD, EMBD);
        n = (long)OBSD*EMBD;
        transpose_k<<<(unsigned)((n+255)/256), 256>>>(p_decw2T, dec_w2, EMBD, OBSD);
        n = (long)2*STOD*EMBD;
        prep_postEmbT_k<<<(unsigned)((n+255)/256), 256>>>(post_w);
        n = (long)4096*DETD;
        prep_whT_k<<<(unsigned)((n+255)/256), 256>>>(prior_w, prior_b, post_w, gru_whh, gru_bhh);
        n = (long)2048*FEATD;
        prep_w1fT_k<<<(unsigned)((n+255)/256), 256>>>(dec_w1, dec_b1, rew_w1, rew_b1);
    }

    // ---- Phase A: time-batched precompute ----
    run128(obs, OBSD, p_encw1T, OBSD, p_embh, EMBD, enc_b1, nullptr, 0,
           RR, EMBD, OBSD, 1);
    run128(p_embh, EMBD, p_encw2T, EMBD, p_emb, EMBD, enc_b2, nullptr, 0,
           RR, EMBD, EMBD, 1);
    run128(p_emb, EMBD, p_postEmbT, EMBD, p_post_emb, 2*STOD, post_b, nullptr, 0,
           RR, 2*STOD, EMBD, 0);
    run128(actions, ACTD, gru_wih + STOD, STOD+ACTD, p_gia, 3*DETD, gru_bih, nullptr, 0,
           RR, 3*DETD, ACTD, 0);

    // ---- Phase B: sequential recurrence (3 launches per step) ----
    for (int t = 0; t < TS; t++) {
        float* S_t = p_S_all + (size_t)t*BB*4096;
        // S_t = h @ [prior | post_h | whh^T] + bias
        run64(p_h, DETD, p_WhT, DETD, S_t, 4096, p_bh, nullptr, 0,
              BB, 4096, DETD, 0);
        // G = z(S_t) @ wih_z^T + gia[t]   (z computed in-loader; bx==0 persists z->feat)
        run64(nullptr, 0, gru_wih, STOD+ACTD, p_G, 3*DETD,
              nullptr, p_gia + (size_t)t*BB*3*DETD, 3*DETD,
              BB, 3*DETD, STOD, 0,
              S_t, p_post_emb + (size_t)t*BB*2*STOD, eps + (size_t)t*BB*STOD,
              p_feat + (size_t)t*BB*FEATD);
        gru_k<<<(BB*DETD)/256, 256>>>(dones, t);
    }

    // ---- Phase C: batched KL + decoder / reward / losses ----
    klbatch_k<<<RR, STOD>>>();
    run128(p_feat, FEATD, p_W1fT, FEATD, p_H1, 2048, p_b1f, nullptr, 0,
           RR, 2048, FEATD, 1);
    run128(p_H1, 2048, p_decw2T, EMBD, p_pred, OBSD, dec_b2, nullptr, 0,
           RR, OBSD, EMBD, 0);
    recon_k<<<RR, 128>>>(obs);
    rew_k<<<RR, 256>>>(rewards, rew_w2, rew_b2);
    final_k<<<1, 256>>>(out);

    (void)in_sizes; (void)n_in; (void)out_size;
}